// round 15
// baseline (speedup 1.0000x reference)
#include <cuda_runtime.h>
#include <cuda_bf16.h>
#include <mma.h>

#define NB   4
#define LEN1 32777
#define M1   4097
#define M2   512
#define CH   256

typedef unsigned long long u64;
typedef unsigned int u32;
using namespace nvcuda;

// ------- static scratch -------
__device__ float g_out1[NB * M1 * CH];
__device__ float g_gt2[NB * M2 * CH];
__device__ float g_gt1_0[NB * CH];
__device__ float g_attn[NB * M1 * 32];
__device__ float g_rowdot[NB * LEN1 * 4];
__device__ float g_sc1[NB];
__device__ float g_sc2[NB * M2];
// precomputed bf16 hi/lo weight smem images (swizzled layout, stride 144 B)
__device__ __align__(16) unsigned char g_wn_hi[4][4][9216];
__device__ __align__(16) unsigned char g_wn_lo[4][4][9216];
__device__ __align__(16) unsigned char g_ws_hi[4][9216];
__device__ __align__(16) unsigned char g_ws_lo[4][9216];

// ---- f32x2 helpers (gt kernel) ----
__device__ __forceinline__ u64 pk2(float v) {
    u64 r; u32 u = __float_as_uint(v);
    asm("mov.b64 %0, {%1, %1};" : "=l"(r) : "r"(u));
    return r;
}
__device__ __forceinline__ void unpk2(u64 v, float& lo, float& hi) {
    u32 a, b;
    asm("mov.b64 {%0, %1}, %2;" : "=r"(a), "=r"(b) : "l"(v));
    lo = __uint_as_float(a); hi = __uint_as_float(b);
}
#define FMA2(d, a, b) asm("fma.rn.f32x2 %0, %1, %2, %0;" : "+l"(d) : "l"(a), "l"(b))

__device__ __forceinline__ u32 pkbf(float lo_v, float hi_v) {
    u32 r;
    asm("cvt.rn.bf16x2.f32 %0, %1, %2;" : "=r"(r) : "f"(hi_v), "f"(lo_v));
    return r;
}

__device__ __forceinline__ void split4(unsigned char* hi, unsigned char* lo, int boff,
                                       float v0, float v1, float v2, float v3) {
    u32 h01 = pkbf(v0, v1), h23 = pkbf(v2, v3);
    float r0 = v0 - __uint_as_float(h01 << 16);
    float r1 = v1 - __uint_as_float(h01 & 0xffff0000u);
    float r2 = v2 - __uint_as_float(h23 << 16);
    float r3 = v3 - __uint_as_float(h23 & 0xffff0000u);
    *(uint2*)(hi + boff) = make_uint2(h01, h23);
    *(uint2*)(lo + boff) = make_uint2(pkbf(r0, r1), pkbf(r2, r3));
}
__device__ __forceinline__ void split1(unsigned char* hi, unsigned char* lo, int boff, float v) {
    u32 h = pkbf(v, 0.f);
    float r = v - __uint_as_float(h << 16);
    u32 l = pkbf(r, 0.f);
    *(unsigned short*)(hi + boff) = (unsigned short)(h & 0xffff);
    *(unsigned short*)(lo + boff) = (unsigned short)(l & 0xffff);
}

// --------------------------------------------------------- finalize
__global__ void finalize_kernel(float* score1, float* score2) {
    int i = blockIdx.x * 256 + threadIdx.x;
    if (i < NB) score1[i] = 1.f - expf(-0.5f * g_sc1[i]);
    if (i < NB * M2) score2[i] = 1.f - expf(-0.5f * g_sc2[i]);
}

// ------------------------------------------------ gt MLP (f32x2, row pairs)
__global__ void __launch_bounds__(256) gt_kernel(
    const float* __restrict__ gt,
    const float* __restrict__ w1, const float* __restrict__ b1,
    const float* __restrict__ w2, const float* __restrict__ b2)
{
    __shared__ float rsT[256][20];
    __shared__ float g1T[256][20];
    int tid = threadIdx.x, r0 = blockIdx.x * 16;

    #pragma unroll
    for (int i = 0; i < 16; i++)
        rsT[tid][i] = gt[(size_t)(r0 + i) * CH + tid];
    __syncthreads();

    u64 acc[8];
    {
        u64 bb = pk2(b1[tid]);
        #pragma unroll
        for (int j = 0; j < 8; j++) acc[j] = bb;
        for (int c = 0; c < CH; c++) {
            u64 w = pk2(w1[c * CH + tid]);
            const ulonglong2* rp = (const ulonglong2*)&rsT[c][0];
            #pragma unroll
            for (int q = 0; q < 4; q++) {
                ulonglong2 a2 = rp[q];
                FMA2(acc[2 * q + 0], a2.x, w);
                FMA2(acc[2 * q + 1], a2.y, w);
            }
        }
    }
    #pragma unroll
    for (int j = 0; j < 8; j++) {
        float lo, hi; unpk2(acc[j], lo, hi);
        g1T[tid][2 * j]     = fmaxf(lo, 0.f);
        g1T[tid][2 * j + 1] = fmaxf(hi, 0.f);
    }
    if ((r0 & 511) == 0)
        g_gt1_0[(r0 >> 9) * CH + tid] = fmaxf(__uint_as_float((u32)acc[0]), 0.f);
    __syncthreads();

    {
        u64 bb = pk2(b2[tid]);
        #pragma unroll
        for (int j = 0; j < 8; j++) acc[j] = bb;
        for (int c = 0; c < CH; c++) {
            u64 w = pk2(w2[c * CH + tid]);
            const ulonglong2* rp = (const ulonglong2*)&g1T[c][0];
            #pragma unroll
            for (int q = 0; q < 4; q++) {
                ulonglong2 a2 = rp[q];
                FMA2(acc[2 * q + 0], a2.x, w);
                FMA2(acc[2 * q + 1], a2.y, w);
            }
        }
    }
    #pragma unroll
    for (int j = 0; j < 8; j++) {
        float lo, hi; unpk2(acc[j], lo, hi);
        g_gt2[(size_t)(r0 + 2 * j)     * CH + tid] = fmaxf(lo, 0.f);
        g_gt2[(size_t)(r0 + 2 * j + 1) * CH + tid] = fmaxf(hi, 0.f);
    }
}

// ------------- per-row attention dots (streaming) + weight-image prep
__global__ void __launch_bounds__(256) rowdot_kernel(
    const float* __restrict__ x, const float* __restrict__ w_att,
    const float* __restrict__ w_node, const float* __restrict__ w_src)
{
    __shared__ float wa_s[1024];
    int tid = threadIdx.x;
    *(float4*)&wa_s[tid * 4] = *(const float4*)&w_att[tid * 4];
    __syncthreads();

    // weight prep (first 20 blocks of batch row 0)
    if (blockIdx.y == 0 && blockIdx.x < 20) {
        int pid = blockIdx.x * 256 + tid;           // 0..5119
        for (int it = pid; it < 16384; it += 5120) {
            int g = it >> 12, rem = it & 4095;
            int kc = rem >> 10, o = (rem >> 4) & 63, cl = rem & 15;
            float4 wv = *(const float4*)(w_node + ((size_t)(g * 64 + o) * 256) + (kc * 16 + cl) * 4);
            split1(g_wn_hi[g][kc], g_wn_lo[g][kc], o * 144 + (0 * 16 + cl) * 2, wv.x);
            split1(g_wn_hi[g][kc], g_wn_lo[g][kc], o * 144 + (1 * 16 + cl) * 2, wv.y);
            split1(g_wn_hi[g][kc], g_wn_lo[g][kc], o * 144 + (2 * 16 + cl) * 2, wv.z);
            split1(g_wn_hi[g][kc], g_wn_lo[g][kc], o * 144 + (3 * 16 + cl) * 2, wv.w);
        }
        for (int it = pid; it < 4096; it += 5120) {
            int g = it >> 10, o = (it >> 4) & 63, qg = it & 15;
            float4 wv = *(const float4*)(w_src + (size_t)(g * 64 + o) * 64 + qg * 4);
            split4(g_ws_hi[g], g_ws_lo[g], o * 144 + qg * 8, wv.x, wv.y, wv.z, wv.w);
        }
    }

    int b = blockIdx.y;
    int r = blockIdx.x * 8 + (tid >> 5);
    if (r >= LEN1) return;
    int lane = tid & 31;
    const float* row = x + ((size_t)b * LEN1 + r) * CH;
    float s0 = 0.f, s1 = 0.f, s2 = 0.f, s3 = 0.f;
    #pragma unroll
    for (int j = 0; j < 8; j++) {
        int c = lane + 32 * j;
        float v = row[c];
        float4 w = *(const float4*)&wa_s[c * 4];
        s0 = fmaf(v, w.x, s0); s1 = fmaf(v, w.y, s1);
        s2 = fmaf(v, w.z, s2); s3 = fmaf(v, w.w, s3);
    }
    #pragma unroll
    for (int s = 16; s > 0; s >>= 1) {
        s0 += __shfl_xor_sync(0xffffffff, s0, s);
        s1 += __shfl_xor_sync(0xffffffff, s1, s);
        s2 += __shfl_xor_sync(0xffffffff, s2, s);
        s3 += __shfl_xor_sync(0xffffffff, s3, s);
    }
    if (lane < 4) {
        float v = (lane == 0) ? s0 : (lane == 1) ? s1 : (lane == 2) ? s2 : s3;
        g_rowdot[((size_t)b * LEN1 + r) * 4 + lane] = v;
    }
}

// ------------------------- softmax over 8 nodes + score-accumulator init
__global__ void __launch_bounds__(256) attn_softmax_kernel(const float* __restrict__ b_att)
{
    int tid = threadIdx.x, b = blockIdx.y;
    int m = blockIdx.x * 8 + (tid >> 5);
    if (blockIdx.x == 0 && tid == 0) g_sc1[b] = 0.f;
    int zi = blockIdx.x * 256 + tid;
    if (zi < M2) g_sc2[(size_t)b * M2 + zi] = 0.f;
    if (m >= M1) return;
    int lane = tid & 31;
    int h = lane & 3;
    float lg = g_rowdot[((size_t)b * LEN1 + m) * 4 + h]
             + g_rowdot[((size_t)b * LEN1 + 8 * m + 1) * 4 + lane]
             + b_att[h];
    float mx = lg;
    #pragma unroll
    for (int msk = 4; msk <= 16; msk <<= 1)
        mx = fmaxf(mx, __shfl_xor_sync(0xffffffff, mx, msk));
    float e = expf(lg - mx);
    float sum = e;
    #pragma unroll
    for (int msk = 4; msk <= 16; msk <<= 1)
        sum += __shfl_xor_sync(0xffffffff, sum, msk);
    g_attn[((size_t)b * M1 + m) * 32 + lane] = e / sum;
}

// ---------------- wmma bf16-split fused conv, P=64 tile, 3 blocks/SM
// warp w: rows (w&3)*16, output cols (w>>2)*32. src conv first -> SRCBUF.
// Weight smem images copied from precomputed global (uint4 copies).
#define OF_BN   0
#define OF_BS   256
#define OF_ATT  512
#define OF_SRC  2560
#define OF_A    18944
#define OF_ALO  (OF_A + 9216)
#define OF_B    (OF_A + 18432)
#define OF_BLO  (OF_B + 9216)
#define SMEM_TOT (OF_B + 18432)

template<int STAGE>
__global__ void __launch_bounds__(256, 3) conv_tc_kernel(
    const float* __restrict__ x_in,
    const float* __restrict__ b_node, const float* __restrict__ b_src,
    float* __restrict__ outp)
{
    constexpr int M  = (STAGE == 1) ? M1 : M2;
    constexpr int LS = (STAGE == 1) ? LEN1 : M1;
    const float* x   = (STAGE == 1) ? x_in : g_out1;
    const float* gtv = (STAGE == 1) ? g_gt1_0 : g_gt2;
    float*       out = (STAGE == 1) ? g_out1 : outp;

    extern __shared__ char sm[];
    float* biasN = (float*)(sm + OF_BN);
    float* biasS = (float*)(sm + OF_BS);
    float (*attn_s)[8] = (float(*)[8])(sm + OF_ATT);
    float* SRCBUF = (float*)(sm + OF_SRC);
    unsigned char *AHI = (unsigned char*)sm + OF_A, *ALO = (unsigned char*)sm + OF_ALO;
    unsigned char *BHI = (unsigned char*)sm + OF_B, *BLO = (unsigned char*)sm + OF_BLO;

    int tid = threadIdx.x, w = tid >> 5, lane = tid & 31;
    int w4 = w & 3, jp = w >> 2;
    int b = blockIdx.y, g = blockIdx.z;
    int m0 = blockIdx.x * 64;
    int vrows = M - m0; if (vrows > 64) vrows = 64;
    int c0 = g * 64;

    if (tid < 64) { biasN[tid] = b_node[c0 + tid]; biasS[tid] = b_src[c0 + tid]; }
    for (int i = tid; i < 64 * 8; i += 256) {
        int p = i >> 3, n = i & 7;
        attn_s[p][n] = (p < vrows)
            ? g_attn[((size_t)b * M1 + m0 + p) * 32 + n * 4 + g] : 0.f;
    }

    const float* node_base = x + ((size_t)b * LS + 8 * (size_t)m0 + 1) * CH + c0;
    const float* src_base  = x + ((size_t)b * LS + m0) * CH + c0;

    const __nv_bfloat16* Ah = (const __nv_bfloat16*)AHI;
    const __nv_bfloat16* Al = (const __nv_bfloat16*)ALO;
    const __nv_bfloat16* Bh = (const __nv_bfloat16*)BHI;
    const __nv_bfloat16* Bl = (const __nv_bfloat16*)BLO;

    // ---- src conv FIRST: K=64 ----
    __syncthreads();
    #pragma unroll
    for (int u = 0; u < 4; u++) {
        int it = tid + u * 256;
        int p = it >> 4, qi = it & 15;
        bool val = p < vrows;
        float4 v = val ? *(const float4*)(src_base + (size_t)p * CH + qi * 4)
                       : make_float4(0.f, 0.f, 0.f, 0.f);
        split4(AHI, ALO, p * 144 + qi * 8, v.x, v.y, v.z, v.w);
    }
    {
        const uint4* sh = (const uint4*)g_ws_hi[g];
        const uint4* sl = (const uint4*)g_ws_lo[g];
        for (int it = tid; it < 576; it += 256) {
            ((uint4*)BHI)[it] = sh[it];
            ((uint4*)BLO)[it] = sl[it];
        }
    }
    __syncthreads();
    {
        wmma::fragment<wmma::accumulator, 16, 16, 16, float> accS[2];
        #pragma unroll
        for (int j = 0; j < 2; j++) wmma::fill_fragment(accS[j], 0.f);
        #pragma unroll
        for (int ks = 0; ks < 4; ks++) {
            wmma::fragment<wmma::matrix_a, 16, 16, 16, __nv_bfloat16, wmma::row_major> ah, al;
            wmma::load_matrix_sync(ah, Ah + (w4 * 16) * 72 + ks * 16, 72);
            wmma::load_matrix_sync(al, Al + (w4 * 16) * 72 + ks * 16, 72);
            #pragma unroll
            for (int j = 0; j < 2; j++) {
                int jc = jp * 2 + j;
                wmma::fragment<wmma::matrix_b, 16, 16, 16, __nv_bfloat16, wmma::col_major> bh, bl;
                wmma::load_matrix_sync(bh, Bh + (jc * 16) * 72 + ks * 16, 72);
                wmma::load_matrix_sync(bl, Bl + (jc * 16) * 72 + ks * 16, 72);
                wmma::mma_sync(accS[j], ah, bh, accS[j]);
                wmma::mma_sync(accS[j], ah, bl, accS[j]);
                wmma::mma_sync(accS[j], al, bh, accS[j]);
            }
        }
        #pragma unroll
        for (int j = 0; j < 2; j++)
            wmma::store_matrix_sync(SRCBUF + (w4 * 16) * 64 + (jp * 2 + j) * 16, accS[j],
                                    64, wmma::mem_row_major);
    }

    // ---- node conv: K=256, 4 chunks of 64 ----
    wmma::fragment<wmma::accumulator, 16, 16, 16, float> accN[2];
    #pragma unroll
    for (int j = 0; j < 2; j++) wmma::fill_fragment(accN[j], 0.f);

    for (int kc = 0; kc < 4; kc++) {
        __syncthreads();
        #pragma unroll
        for (int u = 0; u < 4; u++) {
            int it = tid + u * 256;
            int q = it & 3, rest = it >> 2;
            int p = rest >> 2, t = rest & 3;
            bool val = p < vrows;
            float a0 = val ? attn_s[p][2 * t]     : 0.f;
            float a1 = val ? attn_s[p][2 * t + 1] : 0.f;
            const float* r0 = node_base + (size_t)(8 * p + 2 * t) * CH + kc * 16 + q * 4;
            float4 v0 = val ? *(const float4*)r0        : make_float4(0.f, 0.f, 0.f, 0.f);
            float4 v1 = val ? *(const float4*)(r0 + CH) : make_float4(0.f, 0.f, 0.f, 0.f);
            split4(AHI, ALO, p * 144 + (t * 16 + q * 4) * 2,
                   fmaf(a0, v0.x, a1 * v1.x), fmaf(a0, v0.y, a1 * v1.y),
                   fmaf(a0, v0.z, a1 * v1.z), fmaf(a0, v0.w, a1 * v1.w));
        }
        {
            const uint4* sh = (const uint4*)g_wn_hi[g][kc];
            const uint4* sl = (const uint4*)g_wn_lo[g][kc];
            for (int it = tid; it < 576; it += 256) {
                ((uint4*)BHI)[it] = sh[it];
                ((uint4*)BLO)[it] = sl[it];
            }
        }
        __syncthreads();
        #pragma unroll
        for (int ks = 0; ks < 4; ks++) {
            wmma::fragment<wmma::matrix_a, 16, 16, 16, __nv_bfloat16, wmma::row_major> ah, al;
            wmma::load_matrix_sync(ah, Ah + (w4 * 16) * 72 + ks * 16, 72);
            wmma::load_matrix_sync(al, Al + (w4 * 16) * 72 + ks * 16, 72);
            #pragma unroll
            for (int j = 0; j < 2; j++) {
                int jc = jp * 2 + j;
                wmma::fragment<wmma::matrix_b, 16, 16, 16, __nv_bfloat16, wmma::col_major> bh, bl;
                wmma::load_matrix_sync(bh, Bh + (jc * 16) * 72 + ks * 16, 72);
                wmma::load_matrix_sync(bl, Bl + (jc * 16) * 72 + ks * 16, 72);
                wmma::mma_sync(accN[j], ah, bh, accN[j]);
                wmma::mma_sync(accN[j], ah, bl, accN[j]);
                wmma::mma_sync(accN[j], al, bh, accN[j]);
            }
        }
    }
    __syncthreads();

    // ---- epilogue ----
    float* scr = (float*)(sm + OF_A) + w * (16 * 36);
    #pragma unroll
    for (int j = 0; j < 2; j++)
        wmma::store_matrix_sync(scr + j * 16, accN[j], 36, wmma::mem_row_major);
    __syncwarp();

    int r = lane >> 1, half = lane & 1;
    int mg = m0 + w4 * 16 + r;
    int gc = jp * 32 + half * 16;

    float nv[16];
    {
        const float* srow = scr + r * 36 + half * 16;
        #pragma unroll
        for (int c = 0; c < 16; c++)
            nv[c] = fmaxf(srow[c] + biasN[gc + c], 0.f);
    }
    bool do_sc = (STAGE == 2) ? (mg < M) : (mg == 0);
    if (do_sc) {
        const float* gp = (STAGE == 2)
            ? &gtv[((size_t)b * M + mg) * CH + c0 + gc]
            : &gtv[b * CH + c0 + gc];
        float sc = 0.f;
        #pragma unroll
        for (int c = 0; c < 16; c++) { float d = gp[c] - nv[c]; sc += d * d; }
        if (STAGE == 2) atomicAdd(&g_sc2[(size_t)b * M2 + mg], sc);
        else            atomicAdd(&g_sc1[b], sc);
    }
    if (mg < M) {
        const float* srow = SRCBUF + (w4 * 16 + r) * 64 + gc;
        float* op = out + ((size_t)b * M + mg) * CH + c0 + gc;
        #pragma unroll
        for (int c4 = 0; c4 < 4; c4++) {
            float4 o4;
            o4.x = nv[c4 * 4 + 0] + fmaxf(srow[c4 * 4 + 0] + biasS[gc + c4 * 4 + 0], 0.f);
            o4.y = nv[c4 * 4 + 1] + fmaxf(srow[c4 * 4 + 1] + biasS[gc + c4 * 4 + 1], 0.f);
            o4.z = nv[c4 * 4 + 2] + fmaxf(srow[c4 * 4 + 2] + biasS[gc + c4 * 4 + 2], 0.f);
            o4.w = nv[c4 * 4 + 3] + fmaxf(srow[c4 * 4 + 3] + biasS[gc + c4 * 4 + 3], 0.f);
            *(float4*)(op + c4 * 4) = o4;
        }
    }
}

extern "C" void kernel_launch(void* const* d_in, const int* in_sizes, int n_in,
                              void* d_out, int out_size)
{
    const float* input  = (const float*)d_in[0];
    const float* gt     = (const float*)d_in[1];
    const float* w_att  = (const float*)d_in[2];
    const float* b_att  = (const float*)d_in[3];
    const float* w_gt1  = (const float*)d_in[4];
    const float* b_gt1  = (const float*)d_in[5];
    const float* w_gt2  = (const float*)d_in[6];
    const float* b_gt2  = (const float*)d_in[7];
    const float* w_agg1 = (const float*)d_in[8];
    const float* b_agg1 = (const float*)d_in[9];
    const float* w_src1 = (const float*)d_in[10];
    const float* b_src1 = (const float*)d_in[11];
    const float* w_agg2 = (const float*)d_in[12];
    const float* b_agg2 = (const float*)d_in[13];
    const float* w_src2 = (const float*)d_in[14];
    const float* b_src2 = (const float*)d_in[15];

    float* out    = (float*)d_out;                 // (B*512, 256)
    float* score1 = out + (size_t)NB * M2 * CH;    // (B,)
    float* score2 = score1 + NB;                   // (B*512,)

    cudaFuncSetAttribute(conv_tc_kernel<1>,
                         cudaFuncAttributeMaxDynamicSharedMemorySize, SMEM_TOT);
    cudaFuncSetAttribute(conv_tc_kernel<2>,
                         cudaFuncAttributeMaxDynamicSharedMemorySize, SMEM_TOT);

    // conv1 at captured launch index 3; rowdot(0) also preps stage-1 weight images.
    rowdot_kernel<<<dim3((LEN1 + 7) / 8, NB), 256>>>(input, w_att, w_agg1, w_src1);
    attn_softmax_kernel<<<dim3((M1 + 7) / 8, NB), 256>>>(b_att);
    gt_kernel<<<NB * M2 / 16, 256>>>(gt, w_gt1, b_gt1, w_gt2, b_gt2);
    conv_tc_kernel<1><<<dim3((M1 + 63) / 64, NB, 4), 256, SMEM_TOT>>>(
        input, b_agg1, b_src1, nullptr);
    // re-prep weight images for stage 2, then conv2
    rowdot_kernel<<<dim3(20, 1), 256>>>(input, w_att, w_agg2, w_src2);
    conv_tc_kernel<2><<<dim3(M2 / 64, NB, 4), 256, SMEM_TOT>>>(
        input, b_agg2, b_src2, out);
    finalize_kernel<<<(NB * M2 + 255) / 256, 256>>>(score1, score2);
}